// round 14
// baseline (speedup 1.0000x reference)
#include <cuda_runtime.h>
#include <float.h>

#define N_COLS   32000
#define NV4      8000
#define THREADS  256
#define NWARPS   8
#define CHUNKF4  1024        // float4 per chunk (16 KB)
#define NCHUNK   8           // chunk 7 partial: 832 float4 (13312 B)
#define SEGW     512         // per-warp float4-group capacity (64 KB total)
#define SCALW    512         // per-warp scalar capacity (reuses buffer0)
#define NEWTON   12
#define MAX_ROWS 4096
#define SENT     (-1.0e30f)

__device__ float g_row_loss[MAX_ROWS];
__device__ unsigned g_done = 0;

__device__ __forceinline__ float max4(float4 v) {
    return fmaxf(fmaxf(v.x, v.y), fmaxf(v.z, v.w));
}

__device__ __forceinline__ void mbar_init(unsigned int a, unsigned int cnt) {
    asm volatile("mbarrier.init.shared.b64 [%0], %1;" :: "r"(a), "r"(cnt) : "memory");
}
__device__ __forceinline__ void fence_proxy_async_f() {
    asm volatile("fence.proxy.async;" ::: "memory");
}
__device__ __forceinline__ void mbar_expect(unsigned int a, unsigned int bytes) {
    asm volatile("mbarrier.arrive.expect_tx.shared.b64 _, [%0], %1;" :: "r"(a), "r"(bytes) : "memory");
}
__device__ __forceinline__ void bulk_g2s(unsigned int dst, const void* src,
                                         unsigned int bytes, unsigned int mbar) {
    asm volatile("cp.async.bulk.shared::cluster.global.mbarrier::complete_tx::bytes [%0], [%1], %2, [%3];"
                 :: "r"(dst), "l"(src), "r"(bytes), "r"(mbar) : "memory");
}
__device__ __forceinline__ void mbar_wait(unsigned int mbar, unsigned int parity) {
    asm volatile(
        "{\n\t"
        ".reg .pred P1;\n\t"
        "LAB_WAIT_%=:\n\t"
        "mbarrier.try_wait.parity.acquire.cta.shared::cta.b64 P1, [%0], %1, 0x989680;\n\t"
        "@P1 bra.uni LAB_DONE_%=;\n\t"
        "bra.uni LAB_WAIT_%=;\n\t"
        "LAB_DONE_%=:\n\t"
        "}"
        :: "r"(mbar), "r"(parity) : "memory");
}

__global__ void __launch_bounds__(THREADS)
entmax15_fused(const float* __restrict__ inp, const int* __restrict__ tgt,
               float* __restrict__ out, int rows) {
    extern __shared__ char smemraw[];
    float4* buf = (float4*)smemraw;                        // 32 KB (2 x 16 KB)
    float4* seg = (float4*)(smemraw + 2 * CHUNKF4 * 16);   // 64 KB
    __shared__ unsigned long long mb[2];
    __shared__ float redm[2][NWARPS];
    __shared__ float redA[NWARPS], redB[NWARPS], redC[NWARPS];
    __shared__ int   scnt[NWARPS], scnt2[NWARPS];
    __shared__ int   s_last;
    __shared__ float sred[THREADS];

    const int row  = blockIdx.x;
    const int tid  = threadIdx.x;
    const int lane = tid & 31;
    const int w    = tid >> 5;
    const float* rp = inp + (size_t)row * N_COLS;
    const unsigned lm = (1u << lane) - 1u;

    float4* segw = seg + w * SEGW;

    float tgl = 0.0f;
    if (tid == 0) {
        int ti = tgt[row];
        ti = (ti < 0) ? 0 : ((ti >= N_COLS) ? N_COLS - 1 : ti);
        tgl = __ldg(rp + ti);
    }

    const unsigned int sbase = (unsigned int)__cvta_generic_to_shared(buf);
    const unsigned int mb0 = (unsigned int)__cvta_generic_to_shared(&mb[0]);
    const unsigned int mb1 = (unsigned int)__cvta_generic_to_shared(&mb[1]);

    if (tid == 0) {
        mbar_init(mb0, 1);
        mbar_init(mb1, 1);
        fence_proxy_async_f();
    }
    __syncthreads();
    if (tid == 0) {
        mbar_expect(mb0, 16384u);
        bulk_g2s(sbase,          rp,                16384u, mb0);
        mbar_expect(mb1, 16384u);
        bulk_g2s(sbase + 16384u, rp + CHUNKF4 * 4,  16384u, mb1);
    }

    float lmax = -FLT_MAX;
    float thr  = -FLT_MAX;   // updated block-wide after chunk 0
    int   wcnt = 0;

    #pragma unroll 1
    for (int k = 0; k < NCHUNK; ++k) {
        mbar_wait((k & 1) ? mb1 : mb0, (unsigned)((k >> 1) & 1));

        const float4* bb = buf + ((k & 1) * CHUNKF4) + tid;
        float4 va = bb[0], vb = bb[256], vc = bb[512];
        float4 vd = (k < 7 || tid < 64) ? bb[768] : make_float4(SENT, SENT, SENT, SENT);

        float g0 = max4(va), g1 = max4(vb), g2 = max4(vc), g3 = max4(vd);
        lmax = fmaxf(lmax, fmaxf(fmaxf(g0, g1), fmaxf(g2, g3)));

        // block running max -> threshold (piggybacks on the mandatory barrier)
        float wmx = lmax;
        #pragma unroll
        for (int o = 16; o; o >>= 1) wmx = fmaxf(wmx, __shfl_xor_sync(0xffffffffu, wmx, o));
        if (lane == 0) redm[k & 1][w] = wmx;
        __syncthreads();   // (a) all regs loaded from buffer  (b) redm visible

        // refill this buffer: consumers hold data in regs now
        if (tid == 0 && k + 2 < NCHUNK) {
            unsigned int bytes = (k + 2 < 7) ? 16384u : 13312u;
            unsigned int mba = (k & 1) ? mb1 : mb0;
            mbar_expect(mba, bytes);
            bulk_g2s(sbase + (unsigned)((k & 1) * 16384),
                     rp + (size_t)(k + 2) * CHUNKF4 * 4, bytes, mba);
        }

        float bm = redm[k & 1][0];
        #pragma unroll
        for (int q = 1; q < NWARPS; ++q) bm = fmaxf(bm, redm[k & 1][q]);
        thr = fmaxf(thr, bm - 2.0f);     // bm <= m  =>  never rejects a true candidate

        // one ballot per GROUP; accepted groups stored whole (extras inert later)
        float gm4[4] = {g0, g1, g2, g3};
        float4 vv[4] = {va, vb, vc, vd};
        #pragma unroll
        for (int g = 0; g < 4; ++g) {
            bool p = (gm4[g] >= thr);
            unsigned b = __ballot_sync(0xffffffffu, p);
            if (p) {
                int pos = wcnt + __popc(b & lm);
                if (pos < SEGW) segw[pos] = vv[g];
            }
            wcnt += __popc(b);
        }
    }

    // ---- exact row max + group-overflow check ----
    float wmx = lmax;
    #pragma unroll
    for (int o = 16; o; o >>= 1) wmx = fmaxf(wmx, __shfl_xor_sync(0xffffffffu, wmx, o));
    if (lane == 0) { redA[w] = wmx; scnt[w] = wcnt; }
    __syncthreads();
    float m = redA[0];
    int ovf = 0;
    #pragma unroll
    for (int q = 0; q < NWARPS; ++q) {
        m = fmaxf(m, redA[q]);
        ovf |= (scnt[q] > SEGW);
    }
    const float cthr = m - 2.0f;
    const float cm   = -0.5f * m;

    // ---- compact segments -> true scalars (v >= m-2) into buffer0 (free now) ----
    float* scal = (float*)buf + w * SCALW;   // 8 x 512 floats = 16 KB = buffer0
    int sc = 0;
    const int myc = (wcnt < SEGW) ? wcnt : SEGW;
    for (int j = 0; j < myc; j += 32) {
        int idx = j + lane;
        bool valid = (idx < myc);
        float4 q = valid ? segw[idx] : make_float4(SENT, SENT, SENT, SENT);
        float xe[4] = {q.x, q.y, q.z, q.w};
        #pragma unroll
        for (int e = 0; e < 4; ++e) {
            bool kp = (xe[e] >= cthr);
            unsigned b = __ballot_sync(0xffffffffu, kp);
            if (kp) {
                int pos = sc + __popc(b & lm);
                if (pos < SCALW) scal[pos] = xe[e];
            }
            sc += __popc(b);
        }
    }
    if (lane == 0) scnt2[w] = sc;
    __syncthreads();
    #pragma unroll
    for (int q = 0; q < NWARPS; ++q) ovf |= (scnt2[q] > SCALW);
    const int scc = (sc < SCALW) ? sc : SCALW;

    if (!ovf) {
        // ---- block Newton on raw-v scalars with fused constants ----
        float tau = -1.0f;
        for (int it = 0; it < NEWTON; ++it) {
            float ct = cm - tau;
            float s1 = 0.0f, s2 = 0.0f;
            for (int i = lane; i < scc; i += 32) {
                float d = fmaxf(fmaf(scal[i], 0.5f, ct), 0.0f);
                s1 += d; s2 = fmaf(d, d, s2);
            }
            #pragma unroll
            for (int o = 16; o; o >>= 1) {
                s1 += __shfl_xor_sync(0xffffffffu, s1, o);
                s2 += __shfl_xor_sync(0xffffffffu, s2, o);
            }
            if (lane == 0) { redA[w] = s1; redB[w] = s2; }
            __syncthreads();
            float S1 = 0.0f, S2 = 0.0f;
            #pragma unroll
            for (int q = 0; q < NWARPS; ++q) { S1 += redA[q]; S2 += redB[q]; }
            __syncthreads();
            tau += (S2 - 1.0f) / (2.0f * S1);   // convex f, monotone from below
        }

        float sp = 0.0f, s15 = 0.0f, spx = 0.0f;
        for (int i = lane; i < scc; i += 32) {
            float x = fmaf(scal[i], 0.5f, cm);
            float d = fmaxf(x - tau, 0.0f);
            float p = d * d;
            sp += p; s15 = fmaf(p, d, s15); spx = fmaf(p, x, spx);
        }
        #pragma unroll
        for (int o = 16; o; o >>= 1) {
            sp  += __shfl_xor_sync(0xffffffffu, sp,  o);
            s15 += __shfl_xor_sync(0xffffffffu, s15, o);
            spx += __shfl_xor_sync(0xffffffffu, spx, o);
        }
        if (lane == 0) { redA[w] = sp; redB[w] = s15; redC[w] = spx; }
        __syncthreads();
        if (tid == 0) {
            float SP = 0, S15 = 0, SPX = 0;
            #pragma unroll
            for (int q = 0; q < NWARPS; ++q) { SP += redA[q]; S15 += redB[q]; SPX += redC[q]; }
            float omega = (1.0f - S15) * (4.0f / 3.0f);
            g_row_loss[row] = omega + 2.0f * SPX + m * SP - tgl;
        }
    } else {
        // ---- Fallback (vanishing probability): Newton over GMEM row ----
        const float4* g4 = (const float4*)rp;
        float tau = -1.0f;
        for (int it = 0; it < 14; ++it) {
            float ct = cm - tau;
            float s1 = 0.0f, s2 = 0.0f;
            for (int q = tid; q < NV4; q += THREADS) {
                float4 v = g4[q];
                float x4[4] = {v.x, v.y, v.z, v.w};
                #pragma unroll
                for (int c = 0; c < 4; ++c) {
                    float d = fmaxf(fmaf(x4[c], 0.5f, ct), 0.0f);
                    s1 += d; s2 = fmaf(d, d, s2);
                }
            }
            #pragma unroll
            for (int o = 16; o; o >>= 1) {
                s1 += __shfl_xor_sync(0xffffffffu, s1, o);
                s2 += __shfl_xor_sync(0xffffffffu, s2, o);
            }
            if (lane == 0) { redA[w] = s1; redB[w] = s2; }
            __syncthreads();
            float S1 = 0.0f, S2 = 0.0f;
            #pragma unroll
            for (int q = 0; q < NWARPS; ++q) { S1 += redA[q]; S2 += redB[q]; }
            __syncthreads();
            tau += (S2 - 1.0f) / (2.0f * S1);
        }
        float sp = 0.0f, s15 = 0.0f, spx = 0.0f;
        for (int q = tid; q < NV4; q += THREADS) {
            float4 v = g4[q];
            float x4[4] = {v.x, v.y, v.z, v.w};
            #pragma unroll
            for (int c = 0; c < 4; ++c) {
                float x = fmaf(x4[c], 0.5f, cm);
                float d = fmaxf(x - tau, 0.0f);
                float p = d * d;
                sp += p; s15 = fmaf(p, d, s15); spx = fmaf(p, x, spx);
            }
        }
        #pragma unroll
        for (int o = 16; o; o >>= 1) {
            sp  += __shfl_xor_sync(0xffffffffu, sp,  o);
            s15 += __shfl_xor_sync(0xffffffffu, s15, o);
            spx += __shfl_xor_sync(0xffffffffu, spx, o);
        }
        if (lane == 0) { redA[w] = sp; redB[w] = s15; redC[w] = spx; }
        __syncthreads();
        if (tid == 0) {
            float SP = 0, S15 = 0, SPX = 0;
            #pragma unroll
            for (int q = 0; q < NWARPS; ++q) { SP += redA[q]; S15 += redB[q]; SPX += redC[q]; }
            float omega = (1.0f - S15) * (4.0f / 3.0f);
            g_row_loss[row] = omega + 2.0f * SPX + m * SP - tgl;
        }
    }

    // ---- Completion: last block computes the mean (deterministic order) ----
    if (tid == 0) {
        __threadfence();
        unsigned old = atomicAdd(&g_done, 1u);
        s_last = (old == (unsigned)gridDim.x - 1u);
    }
    __syncthreads();
    if (s_last) {
        __threadfence();
        float v = 0.0f;
        for (int i = tid; i < rows; i += THREADS) v += g_row_loss[i];
        sred[tid] = v;
        __syncthreads();
        #pragma unroll
        for (int st = THREADS / 2; st; st >>= 1) {
            if (tid < st) sred[tid] += sred[tid + st];
            __syncthreads();
        }
        if (tid == 0) {
            out[0] = sred[0] / (float)rows;
            g_done = 0;   // reset for next graph replay
        }
    }
}

extern "C" void kernel_launch(void* const* d_in, const int* in_sizes, int n_in,
                              void* d_out, int out_size) {
    const float* inp = (const float*)d_in[0];
    const int*   tgt = (const int*)d_in[1];
    float*       out = (float*)d_out;
    const int rows = in_sizes[1];  // 4096

    const int dyn = 2 * CHUNKF4 * 16 + NWARPS * SEGW * 16;   // 32 KB + 64 KB
    cudaFuncSetAttribute(entmax15_fused, cudaFuncAttributeMaxDynamicSharedMemorySize, dyn);
    entmax15_fused<<<rows, THREADS, dyn>>>(inp, tgt, out, rows);
}